// round 8
// baseline (speedup 1.0000x reference)
#include <cuda_runtime.h>
#include <cuda_bf16.h>
#include <math_constants.h>

#define B 4
#define NPTS 1024
#define KNB 80

// ---------------- scratch (device globals) ----------------
__device__ int   g_idx[B * NPTS * KNB];
__device__ float g_u[(size_t)B * NPTS * 128];
__device__ float g_v[(size_t)B * NPTS * 128];
__device__ double g_gs[48];
__device__ unsigned int g_ymax[B * 1024];
__device__ unsigned int g_ymin[B * 1024];
__device__ double g_gs5[64];
__device__ unsigned int g_cnt;
__device__ unsigned int g_flag;

__device__ __forceinline__ unsigned int fenc(float f) {
    unsigned int b = __float_as_uint(f);
    return (b & 0x80000000u) ? ~b : (b | 0x80000000u);
}
__device__ __forceinline__ float fdec(unsigned int u) {
    unsigned int b = (u & 0x80000000u) ? (u & 0x7FFFFFFFu) : ~u;
    return __uint_as_float(b);
}

// software grid barrier (co-resident grids only; epoch monotone per replay)
__device__ __forceinline__ void grid_barrier(unsigned int epoch, unsigned int nb) {
    __threadfence();
    __syncthreads();
    if (threadIdx.x == 0) {
        unsigned int a = atomicAdd(&g_cnt, 1u);
        if (a == nb - 1u) { g_cnt = 0u; __threadfence(); atomicExch(&g_flag, epoch); }
        while (atomicAdd(&g_flag, 0u) < epoch) __nanosleep(64);
    }
    __syncthreads();
}

// ---------------- zero/re-arm kernel (runs first every replay) ----------------
__global__ void zero_all_kernel() {
    int i = blockIdx.x * 256 + threadIdx.x;
    if (i < B * 1024) { g_ymax[i] = 0u; g_ymin[i] = 0xFFFFFFFFu; }
    if (i < 48) g_gs[i] = 0.0;
    if (i < 64) g_gs5[i] = 0.0;
    if (i == 0) { g_cnt = 0u; g_flag = 0u; }
}

// =====================================================================================
// front_kernel v2: fused gram + knn + u/v.  grid (64, B) = 256 blocks, 256 thr,
// 16 points/block, 2 rows/warp, dyn smem ~109 KB -> 2 CTAs/SM.
// =====================================================================================
#define FRONT_SMEM ((16 * 1024 + 8448 + 1024 + 2048) * 4)

__global__ __launch_bounds__(256) void front_kernel(const float* __restrict__ x, int bstride,
                                                    int C, const float* __restrict__ W, int Cout) {
    extern __shared__ float smf[];
    unsigned int* ukeys = (unsigned int*)smf;      // 16 rows x 1024 keys (64 KB)
    float* ctile = smf + 16 * 1024;                // 64 x 132 (33 KB)
    float* xrow  = ctile + 8448;                   // 16 x 64  (4 KB)
    int*   hist  = (int*)(xrow + 1024);            // 8 warps x 256 bins (8 KB)

    int t = threadIdx.x, lane = t & 31, w = t >> 5;
    int b = blockIdx.y, n0 = blockIdx.x * 16;
    const float* xb = x + (size_t)b * bstride;

    for (int i = t; i < 16 * C; i += 256) {
        int r = i & 15, c = i >> 4;
        xrow[r * 64 + c] = xb[(size_t)c * NPTS + n0 + r];
    }
    int r0 = 2 * w, r1 = 2 * w + 1;

    // ---- phase A: keys[r][m] = fenc(2*dot(r,m) - |x_m|^2) (|x_r|^2 dropped: rank-invariant)
    for (int tile = 0; tile < 8; tile++) {
        int m0 = tile << 7;
        __syncthreads();
        for (int i = t; i < (C << 7); i += 256) {
            int c = i >> 7, l = i & 127;
            ctile[c * 132 + l] = xb[(size_t)c * NPTS + m0 + l];
        }
        __syncthreads();
        float a0[4] = {}, a1[4] = {}, sb[4] = {};
        for (int c = 0; c < C; c++) {
            float4 cv = *(const float4*)&ctile[c * 132 + (lane << 2)];
            float x0 = xrow[r0 * 64 + c], x1 = xrow[r1 * 64 + c];
            sb[0] = fmaf(cv.x, cv.x, sb[0]); sb[1] = fmaf(cv.y, cv.y, sb[1]);
            sb[2] = fmaf(cv.z, cv.z, sb[2]); sb[3] = fmaf(cv.w, cv.w, sb[3]);
            a0[0] = fmaf(x0, cv.x, a0[0]); a0[1] = fmaf(x0, cv.y, a0[1]);
            a0[2] = fmaf(x0, cv.z, a0[2]); a0[3] = fmaf(x0, cv.w, a0[3]);
            a1[0] = fmaf(x1, cv.x, a1[0]); a1[1] = fmaf(x1, cv.y, a1[1]);
            a1[2] = fmaf(x1, cv.z, a1[2]); a1[3] = fmaf(x1, cv.w, a1[3]);
        }
        ((uint4*)(ukeys + r0 * 1024 + m0))[lane] =
            make_uint4(fenc(2.f*a0[0]-sb[0]), fenc(2.f*a0[1]-sb[1]),
                       fenc(2.f*a0[2]-sb[2]), fenc(2.f*a0[3]-sb[3]));
        ((uint4*)(ukeys + r1 * 1024 + m0))[lane] =
            make_uint4(fenc(2.f*a1[0]-sb[0]), fenc(2.f*a1[1]-sb[1]),
                       fenc(2.f*a1[2]-sb[2]), fenc(2.f*a1[3]-sb[3]));
    }
    __syncwarp();   // each warp reads only its own rows below

    // ---- phase B: per-warp top-80 radix select (2 rows per warp) ----
    int* myhist = hist + w * 256;
    for (int ri = 0; ri < 2; ri++) {
        int r = 2 * w + ri;
        const unsigned int* rowkeys = ukeys + r * 1024;
        unsigned int rk[32];
#pragma unroll
        for (int j = 0; j < 32; j++) rk[j] = rowkeys[lane + 32 * j];

        unsigned int prefix = 0, pmask = 0;
        int need = KNB;
        for (int shift = 24; shift >= 0; shift -= 8) {
#pragma unroll
            for (int j = 0; j < 8; j++) myhist[lane + 32 * j] = 0;
            __syncwarp();
#pragma unroll
            for (int j = 0; j < 32; j++) {
                unsigned int k = rk[j];
                if ((k & pmask) == prefix) atomicAdd(&myhist[(k >> shift) & 255], 1);
            }
            __syncwarp();
            int cnt8[8], sloc[8];
#pragma unroll
            for (int jj = 0; jj < 8; jj++) cnt8[jj] = myhist[lane * 8 + jj];
            int tot = 0;
#pragma unroll
            for (int jj = 7; jj >= 0; jj--) { tot += cnt8[jj]; sloc[jj] = tot; }
            int incl = tot;
#pragma unroll
            for (int off = 1; off < 32; off <<= 1) {
                int o = __shfl_down_sync(0xffffffffu, incl, off);
                if (lane + off < 32) incl += o;
            }
            int above = incl - tot;
            int found = -1, abv = 0;
#pragma unroll
            for (int jj = 0; jj < 8; jj++) {
                int S = sloc[jj] + above;
                int nxt = S - cnt8[jj];
                if (S >= need && nxt < need) { found = lane * 8 + jj; abv = nxt; }
            }
            unsigned int bal = __ballot_sync(0xffffffffu, found >= 0);
            int src = __ffs(bal) - 1;
            int bsel = __shfl_sync(0xffffffffu, found, src);
            need -= __shfl_sync(0xffffffffu, abv, src);
            prefix |= ((unsigned int)bsel) << shift;
            pmask |= 255u << shift;
            __syncwarp();
        }
        int* outp = g_idx + ((b << 10) + n0 + r) * KNB;
        int cgt = 0;
#pragma unroll
        for (int j = 0; j < 32; j++) {
            unsigned int k = rk[j];
            bool gt = (k > prefix);
            unsigned int bal = __ballot_sync(0xffffffffu, gt);
            if (gt) outp[cgt + __popc(bal & ((1u << lane) - 1u))] = lane + 32 * j;
            cgt += __popc(bal);
        }
        int taken = 0;
        for (int j = 0; j < 32 && taken < need; j++) {
            unsigned int k = rk[j];
            bool eq = (k == prefix);
            unsigned int bal = __ballot_sync(0xffffffffu, eq);
            int pos = __popc(bal & ((1u << lane) - 1u));
            if (eq && (taken + pos) < need) outp[cgt + taken + pos] = lane + 32 * j;
            taken += __popc(bal);
        }
    }

    // ---- phase C: u/v projections for own 16 points (xrow still resident) ----
    int twoC = 2 * C;
    int sh = (Cout == 128) ? 7 : 6;
    for (int i = t; i < 16 * Cout; i += 256) {
        int nl = i >> sh, o = i & (Cout - 1);
        const float* wr = W + (size_t)o * twoC;
        float u = 0.f, v = 0.f;
        for (int c = 0; c < C; c++) {
            float xv = xrow[nl * 64 + c];
            float w1 = wr[c];
            u = fmaf(w1, xv, u);
            v = fmaf(wr[C + c] - w1, xv, v);
        }
        size_t bn = (size_t)((b << 10) + n0 + nl);
        g_u[bn * Cout + o] = u;
        g_v[bn * Cout + o] = v;
    }
}

// =====================================================================================
// back_kernel: gather + stats + grid barrier + GN + leaky + write feat
// grid 256 blocks x 256 thr, 16 points/block.
// =====================================================================================
__global__ __launch_bounds__(256) void back_kernel(int Cout, int gsoff, unsigned int epoch,
                                                   const float* __restrict__ gnw,
                                                   const float* __restrict__ gnb,
                                                   float* __restrict__ feat, int choff) {
    __shared__ int sidx[16 * KNB];
    __shared__ double sacc[4];
    int t = threadIdx.x, lane = t & 31;
    int TPP = Cout >> 2;              // 16 or 32 lanes per point
    int ppb = 256 / TPP;              // 16 or 8 points per pass
    int passes = 16 / ppb;            // 1 or 2
    int bn0 = blockIdx.x * 16;
    int b = bn0 >> 10;
    int o4 = t % TPP;
    int pl0 = t / TPP;

    if (t < 4) sacc[t] = 0.0;
    for (int i = t; i < 16 * KNB; i += 256) sidx[i] = g_idx[bn0 * KNB + i];
    __syncthreads();

    const float4* ub = (const float4*)g_u + (size_t)(b << 10) * TPP;
    int half = TPP >> 1;
    int g = o4 / half;
    float4 rymx[2], rymn[2];
    const float Kf = (float)KNB;

    for (int p = 0; p < passes; p++) {
        int pl = p * ppb + pl0;
        int bn = bn0 + pl;
        const int* myidx = sidx + pl * KNB;
        float4 mx = make_float4(-CUDART_INF_F, -CUDART_INF_F, -CUDART_INF_F, -CUDART_INF_F);
        float4 mn = make_float4(CUDART_INF_F, CUDART_INF_F, CUDART_INF_F, CUDART_INF_F);
        float4 s1 = make_float4(0, 0, 0, 0), s2 = make_float4(0, 0, 0, 0);
        for (int k = 0; k < KNB; k += 4) {
            float4 v0 = ub[(size_t)myidx[k] * TPP + o4];
            float4 v1 = ub[(size_t)myidx[k + 1] * TPP + o4];
            float4 v2 = ub[(size_t)myidx[k + 2] * TPP + o4];
            float4 v3 = ub[(size_t)myidx[k + 3] * TPP + o4];
#define ACC(vv) \
            mx.x = fmaxf(mx.x, vv.x); mn.x = fminf(mn.x, vv.x); s1.x += vv.x; s2.x = fmaf(vv.x, vv.x, s2.x); \
            mx.y = fmaxf(mx.y, vv.y); mn.y = fminf(mn.y, vv.y); s1.y += vv.y; s2.y = fmaf(vv.y, vv.y, s2.y); \
            mx.z = fmaxf(mx.z, vv.z); mn.z = fminf(mn.z, vv.z); s1.z += vv.z; s2.z = fmaf(vv.z, vv.z, s2.z); \
            mx.w = fmaxf(mx.w, vv.w); mn.w = fminf(mn.w, vv.w); s1.w += vv.w; s2.w = fmaf(vv.w, vv.w, s2.w);
            ACC(v0) ACC(v1) ACC(v2) ACC(v3)
#undef ACC
        }
        float4 v = ((const float4*)g_v)[(size_t)bn * TPP + o4];
        rymx[p] = make_float4(mx.x + v.x, mx.y + v.y, mx.z + v.z, mx.w + v.w);
        rymn[p] = make_float4(mn.x + v.x, mn.y + v.y, mn.z + v.z, mn.w + v.w);
        float S1 = (s1.x + Kf * v.x) + (s1.y + Kf * v.y) + (s1.z + Kf * v.z) + (s1.w + Kf * v.w);
        float S2 = (s2.x + 2.f * v.x * s1.x + Kf * v.x * v.x)
                 + (s2.y + 2.f * v.y * s1.y + Kf * v.y * v.y)
                 + (s2.z + 2.f * v.z * s1.z + Kf * v.z * v.z)
                 + (s2.w + 2.f * v.w * s1.w + Kf * v.w * v.w);
#pragma unroll
        for (int off = 8; off > 0; off >>= 1) {
            if (off < half) {
                S1 += __shfl_down_sync(0xffffffffu, S1, off, half);
                S2 += __shfl_down_sync(0xffffffffu, S2, off, half);
            }
        }
        if ((lane & (half - 1)) == 0) {
            int gg = (lane / half) & 1;
            atomicAdd(&sacc[gg * 2 + 0], (double)S1);
            atomicAdd(&sacc[gg * 2 + 1], (double)S2);
        }
    }
    __syncthreads();
    if (t < 4) atomicAdd(&g_gs[gsoff + (b * 2 + (t >> 1)) * 2 + (t & 1)], sacc[t]);

    grid_barrier(epoch, 256u);

    double cntr = (double)(Cout >> 1) * (double)NPTS * (double)KNB;
    double S1g = atomicAdd(&g_gs[gsoff + (b * 2 + g) * 2 + 0], 0.0);
    double S2g = atomicAdd(&g_gs[gsoff + (b * 2 + g) * 2 + 1], 0.0);
    double mud = S1g / cntr;
    float var = (float)(S2g / cntr - mud * mud);
    float rsq = rsqrtf(var + 1e-5f);
    float mu = (float)mud;
    float A[4], Bb[4];
#pragma unroll
    for (int j = 0; j < 4; j++) {
        int o = 4 * o4 + j;
        A[j] = gnw[o] * rsq;
        Bb[j] = gnb[o] - mu * A[j];
    }
    for (int p = 0; p < passes; p++) {
        int pl = p * ppb + pl0;
        int n = (bn0 & 1023) + pl;
        float* fb = feat + (size_t)b * 262144 + (size_t)choff * NPTS + n;
        float mxv[4] = { rymx[p].x, rymx[p].y, rymx[p].z, rymx[p].w };
        float mnv[4] = { rymn[p].x, rymn[p].y, rymn[p].z, rymn[p].w };
#pragma unroll
        for (int j = 0; j < 4; j++) {
            float c1 = fmaf(A[j], mxv[j], Bb[j]);
            float c2 = fmaf(A[j], mnv[j], Bb[j]);
            c1 = c1 >= 0.f ? c1 : 0.2f * c1;
            c2 = c2 >= 0.f ? c2 : 0.2f * c2;
            fb[(size_t)(4 * o4 + j) * NPTS] = fmaxf(c1, c2);
        }
    }
}

// =====================================================================================
// tail_kernel: final matmul (128x128 tiles) + stats + grid barrier + GN/relu/max output
// =====================================================================================
__global__ __launch_bounds__(256, 2) void tail_kernel(const float* __restrict__ feat,
                                                      const float* __restrict__ W,
                                                      const float* __restrict__ bias,
                                                      const float* __restrict__ gnw,
                                                      const float* __restrict__ gnb,
                                                      float* __restrict__ out) {
    int b = blockIdx.z;
    int co0 = blockIdx.x * 128, n0 = blockIdx.y * 128;
    __shared__ float Ws[32][132];
    __shared__ float Xs[32][128];
    int t = threadIdx.x, tx = t & 15, ty = t >> 4;
    int lane = t & 31, w = t >> 5;
    float acc[8][8] = {};
    const float* fb = feat + (size_t)b * 262144;
    for (int cc = 0; cc < 256; cc += 32) {
        for (int i = t; i < 32 * 128; i += 256) {
            int row = i >> 5, c = i & 31;
            Ws[c][row] = W[(size_t)(co0 + row) * 256 + cc + c];
        }
        for (int i = t; i < 32 * 128; i += 256) {
            int nl = i & 127, c = i >> 7;
            Xs[c][nl] = fb[(size_t)(cc + c) * NPTS + n0 + nl];
        }
        __syncthreads();
#pragma unroll
        for (int c = 0; c < 32; c++) {
            float wv[8], xv[8];
            const float4* w4 = (const float4*)&Ws[c][ty * 8];
            const float4* x4 = (const float4*)&Xs[c][tx * 8];
            float4 p0 = w4[0], p1 = w4[1], q0 = x4[0], q1 = x4[1];
            wv[0]=p0.x;wv[1]=p0.y;wv[2]=p0.z;wv[3]=p0.w;wv[4]=p1.x;wv[5]=p1.y;wv[6]=p1.z;wv[7]=p1.w;
            xv[0]=q0.x;xv[1]=q0.y;xv[2]=q0.z;xv[3]=q0.w;xv[4]=q1.x;xv[5]=q1.y;xv[6]=q1.z;xv[7]=q1.w;
#pragma unroll
            for (int i = 0; i < 8; i++)
#pragma unroll
                for (int j = 0; j < 8; j++) acc[i][j] = fmaf(wv[i], xv[j], acc[i][j]);
        }
        __syncthreads();
    }
    float s1t = 0.f, s2t = 0.f;
#pragma unroll
    for (int i = 0; i < 8; i++) {
        int co = co0 + ty * 8 + i;
        float bv = bias[co];
        float mx = -CUDART_INF_F, mn = CUDART_INF_F;
#pragma unroll
        for (int j = 0; j < 8; j++) {
            float y = acc[i][j] + bv;
            mx = fmaxf(mx, y); mn = fminf(mn, y);
            s1t += y; s2t = fmaf(y, y, s2t);
        }
#pragma unroll
        for (int off = 8; off > 0; off >>= 1) {
            mx = fmaxf(mx, __shfl_down_sync(0xffffffffu, mx, off, 16));
            mn = fminf(mn, __shfl_down_sync(0xffffffffu, mn, off, 16));
        }
        if (tx == 0) {
            atomicMax(&g_ymax[b * 1024 + co], fenc(mx));
            atomicMin(&g_ymin[b * 1024 + co], fenc(mn));
        }
    }
#pragma unroll
    for (int off = 16; off > 0; off >>= 1) {
        s1t += __shfl_down_sync(0xffffffffu, s1t, off);
        s2t += __shfl_down_sync(0xffffffffu, s2t, off);
    }
    __shared__ double sred[8][2];
    if (lane == 0) { sred[w][0] = (double)s1t; sred[w][1] = (double)s2t; }
    __syncthreads();
    if (t == 0) {
        double a = 0.0, c = 0.0;
        for (int i = 0; i < 8; i++) { a += sred[i][0]; c += sred[i][1]; }
        atomicAdd(&g_gs5[(b * 8 + blockIdx.x) * 2 + 0], a);
        atomicAdd(&g_gs5[(b * 8 + blockIdx.x) * 2 + 1], c);
    }

    grid_barrier(4u, 256u);

    if (t < 16) {
        int bid = blockIdx.x + (blockIdx.y << 3) + ((int)blockIdx.z << 6);
        int i = bid * 16 + t;
        int ob = i >> 10, c = i & 1023;
        int g = c >> 7;
        double cntr = 128.0 * 1024.0;
        double S1 = atomicAdd(&g_gs5[(ob * 8 + g) * 2 + 0], 0.0);
        double S2 = atomicAdd(&g_gs5[(ob * 8 + g) * 2 + 1], 0.0);
        double mud = S1 / cntr;
        float var = (float)(S2 / cntr - mud * mud);
        float rsq = rsqrtf(var + 1e-5f);
        float a = gnw[c] * rsq;
        float bb = gnb[c] - (float)mud * a;
        float ymx = fdec(atomicAdd(&g_ymax[i], 0u));
        float ymn = fdec(atomicAdd(&g_ymin[i], 0u));
        float c1 = fmaxf(fmaf(a, ymx, bb), 0.f);
        float c2 = fmaxf(fmaf(a, ymn, bb), 0.f);
        out[i] = fmaxf(c1, c2);
    }
}

// ---------------- launch ----------------
extern "C" void kernel_launch(void* const* d_in, const int* in_sizes, int n_in,
                              void* d_out, int out_size) {
    const float* x    = (const float*)d_in[0];
    const float* c1w  = (const float*)d_in[1];
    const float* g1w  = (const float*)d_in[2];
    const float* g1b  = (const float*)d_in[3];
    const float* c2w  = (const float*)d_in[4];
    const float* g2w  = (const float*)d_in[5];
    const float* g2b  = (const float*)d_in[6];
    const float* c3w  = (const float*)d_in[7];
    const float* g3w  = (const float*)d_in[8];
    const float* g3b  = (const float*)d_in[9];
    const float* mlpw = (const float*)d_in[10];
    const float* mlpb = (const float*)d_in[11];
    const float* g5w  = (const float*)d_in[12];
    const float* g5b  = (const float*)d_in[13];

    float* out  = (float*)d_out;
    float* feat = out + B * 1024;  // x_features region (B,256,N)

    cudaFuncSetAttribute(front_kernel, cudaFuncAttributeMaxDynamicSharedMemorySize, FRONT_SMEM);

    struct L { const float* xin; int bstride, Cin, Cout, choff, gsoff;
               const float* W; const float* gw; const float* gb; };
    L layers[3] = {
        { x,                3 * NPTS,   3,  64,  0,   0,  c1w, g1w, g1b },
        { feat,             256 * NPTS, 64, 64,  64,  16, c2w, g2w, g2b },
        { feat + 64 * NPTS, 256 * NPTS, 64, 128, 128, 32, c3w, g3w, g3b },
    };

    zero_all_kernel<<<16, 256>>>();

    for (int li = 0; li < 3; li++) {
        L& l = layers[li];
        front_kernel<<<dim3(64, B), 256, FRONT_SMEM>>>(l.xin, l.bstride, l.Cin, l.W, l.Cout);
        back_kernel<<<256, 256>>>(l.Cout, l.gsoff, (unsigned int)(li + 1), l.gw, l.gb, feat, l.choff);
    }

    tail_kernel<<<dim3(8, 8, B), 256>>>(feat, mlpw, mlpb, g5w, g5b, out);
}

// round 9
// speedup vs baseline: 1.3917x; 1.3917x over previous
#include <cuda_runtime.h>
#include <cuda_bf16.h>
#include <math_constants.h>

#define B 4
#define NPTS 1024
#define KNB 80

// ---------------- scratch (device globals) ----------------
__device__ int   g_idx[B * NPTS * KNB];
__device__ float g_u[(size_t)B * NPTS * 128];
__device__ float g_v[(size_t)B * NPTS * 128];
__device__ double g_gs[48];
__device__ unsigned int g_ymax[B * 1024];
__device__ unsigned int g_ymin[B * 1024];
__device__ double g_gs5[64];
__device__ unsigned int g_cnt;
__device__ unsigned int g_flag;

__device__ __forceinline__ unsigned int fenc(float f) {
    unsigned int b = __float_as_uint(f);
    return (b & 0x80000000u) ? ~b : (b | 0x80000000u);
}
__device__ __forceinline__ float fdec(unsigned int u) {
    unsigned int b = (u & 0x80000000u) ? (u & 0x7FFFFFFFu) : ~u;
    return __uint_as_float(b);
}

// software grid barrier (co-resident grids only; epoch monotone per replay)
__device__ __forceinline__ void grid_barrier(unsigned int epoch, unsigned int nb) {
    __threadfence();
    __syncthreads();
    if (threadIdx.x == 0) {
        unsigned int a = atomicAdd(&g_cnt, 1u);
        if (a == nb - 1u) { g_cnt = 0u; __threadfence(); atomicExch(&g_flag, epoch); }
        while (atomicAdd(&g_flag, 0u) < epoch) __nanosleep(64);
    }
    __syncthreads();
}

// ---------------- zero/re-arm kernel (runs first every replay) ----------------
__global__ void zero_all_kernel() {
    int i = blockIdx.x * 256 + threadIdx.x;
    if (i < B * 1024) { g_ymax[i] = 0u; g_ymin[i] = 0xFFFFFFFFu; }
    if (i < 48) g_gs[i] = 0.0;
    if (i < 64) g_gs5[i] = 0.0;
    if (i == 0) { g_cnt = 0u; g_flag = 0u; }
}

// =====================================================================================
// front_kernel v3: fused gram + knn + u/v.  grid (64, B) = 256 blocks, 256 thr,
// 16 points/block, 2 rows/warp, dyn smem ~109 KB -> 2 CTAs/SM.
// Histogram atomics are warp-aggregated via __match_any_sync (pass-1 keys are
// massively bin-concentrated; plain atomics serialize at the ATOMS unit).
// =====================================================================================
#define FRONT_SMEM ((16 * 1024 + 8448 + 1024 + 2048) * 4)

template<int C, int COUT>
__global__ __launch_bounds__(256) void front_kernel(const float* __restrict__ x, int bstride,
                                                    const float* __restrict__ W) {
    extern __shared__ float smf[];
    unsigned int* ukeys = (unsigned int*)smf;      // 16 rows x 1024 keys (64 KB)
    float* ctile = smf + 16 * 1024;                // 64 x 132 (33 KB)
    float* xrow  = ctile + 8448;                   // 16 x 64  (4 KB)
    int*   hist  = (int*)(xrow + 1024);            // 8 warps x 256 bins (8 KB)

    int t = threadIdx.x, lane = t & 31, w = t >> 5;
    int b = blockIdx.y, n0 = blockIdx.x * 16;
    const float* xb = x + (size_t)b * bstride;

    for (int i = t; i < 16 * C; i += 256) {
        int r = i & 15, c = i >> 4;
        xrow[r * 64 + c] = xb[(size_t)c * NPTS + n0 + r];
    }
    int r0 = 2 * w, r1 = 2 * w + 1;

    // ---- phase A: keys[r][m] = fenc(2*dot(r,m) - |x_m|^2) (|x_r|^2 dropped: rank-invariant)
    for (int tile = 0; tile < 8; tile++) {
        int m0 = tile << 7;
        __syncthreads();
        for (int i = t; i < (C << 7); i += 256) {
            int c = i >> 7, l = i & 127;
            ctile[c * 132 + l] = xb[(size_t)c * NPTS + m0 + l];
        }
        __syncthreads();
        float a0[4] = {}, a1[4] = {}, sb[4] = {};
#pragma unroll
        for (int c = 0; c < C; c++) {
            float4 cv = *(const float4*)&ctile[c * 132 + (lane << 2)];
            float x0 = xrow[r0 * 64 + c], x1 = xrow[r1 * 64 + c];
            sb[0] = fmaf(cv.x, cv.x, sb[0]); sb[1] = fmaf(cv.y, cv.y, sb[1]);
            sb[2] = fmaf(cv.z, cv.z, sb[2]); sb[3] = fmaf(cv.w, cv.w, sb[3]);
            a0[0] = fmaf(x0, cv.x, a0[0]); a0[1] = fmaf(x0, cv.y, a0[1]);
            a0[2] = fmaf(x0, cv.z, a0[2]); a0[3] = fmaf(x0, cv.w, a0[3]);
            a1[0] = fmaf(x1, cv.x, a1[0]); a1[1] = fmaf(x1, cv.y, a1[1]);
            a1[2] = fmaf(x1, cv.z, a1[2]); a1[3] = fmaf(x1, cv.w, a1[3]);
        }
        ((uint4*)(ukeys + r0 * 1024 + m0))[lane] =
            make_uint4(fenc(2.f*a0[0]-sb[0]), fenc(2.f*a0[1]-sb[1]),
                       fenc(2.f*a0[2]-sb[2]), fenc(2.f*a0[3]-sb[3]));
        ((uint4*)(ukeys + r1 * 1024 + m0))[lane] =
            make_uint4(fenc(2.f*a1[0]-sb[0]), fenc(2.f*a1[1]-sb[1]),
                       fenc(2.f*a1[2]-sb[2]), fenc(2.f*a1[3]-sb[3]));
    }
    __syncwarp();   // each warp reads only its own rows below

    // ---- phase B: per-warp top-80 radix select (2 rows per warp) ----
    int* myhist = hist + w * 256;
    for (int ri = 0; ri < 2; ri++) {
        int r = 2 * w + ri;
        const unsigned int* rowkeys = ukeys + r * 1024;
        unsigned int rk[32];
#pragma unroll
        for (int j = 0; j < 32; j++) rk[j] = rowkeys[lane + 32 * j];

        unsigned int prefix = 0, pmask = 0;
        int need = KNB;
        for (int shift = 24; shift >= 0; shift -= 8) {
#pragma unroll
            for (int j = 0; j < 8; j++) myhist[lane + 32 * j] = 0;
            __syncwarp();
#pragma unroll
            for (int j = 0; j < 32; j++) {
                unsigned int k = rk[j];
                bool act = ((k & pmask) == prefix);
                int bin = act ? (int)((k >> shift) & 255) : (256 + lane);
                unsigned int m = __match_any_sync(0xffffffffu, bin);
                if (act && ((m & ((1u << lane) - 1u)) == 0u))
                    atomicAdd(&myhist[bin], __popc(m));
            }
            __syncwarp();
            int cnt8[8], sloc[8];
#pragma unroll
            for (int jj = 0; jj < 8; jj++) cnt8[jj] = myhist[lane * 8 + jj];
            int tot = 0;
#pragma unroll
            for (int jj = 7; jj >= 0; jj--) { tot += cnt8[jj]; sloc[jj] = tot; }
            int incl = tot;
#pragma unroll
            for (int off = 1; off < 32; off <<= 1) {
                int o = __shfl_down_sync(0xffffffffu, incl, off);
                if (lane + off < 32) incl += o;
            }
            int above = incl - tot;
            int found = -1, abv = 0;
#pragma unroll
            for (int jj = 0; jj < 8; jj++) {
                int S = sloc[jj] + above;
                int nxt = S - cnt8[jj];
                if (S >= need && nxt < need) { found = lane * 8 + jj; abv = nxt; }
            }
            unsigned int bal = __ballot_sync(0xffffffffu, found >= 0);
            int src = __ffs(bal) - 1;
            int bsel = __shfl_sync(0xffffffffu, found, src);
            need -= __shfl_sync(0xffffffffu, abv, src);
            prefix |= ((unsigned int)bsel) << shift;
            pmask |= 255u << shift;
            __syncwarp();
        }
        int* outp = g_idx + ((b << 10) + n0 + r) * KNB;
        int cgt = 0;
#pragma unroll
        for (int j = 0; j < 32; j++) {
            unsigned int k = rk[j];
            bool gt = (k > prefix);
            unsigned int bal = __ballot_sync(0xffffffffu, gt);
            if (gt) outp[cgt + __popc(bal & ((1u << lane) - 1u))] = lane + 32 * j;
            cgt += __popc(bal);
        }
        int taken = 0;
        for (int j = 0; j < 32 && taken < need; j++) {
            unsigned int k = rk[j];
            bool eq = (k == prefix);
            unsigned int bal = __ballot_sync(0xffffffffu, eq);
            int pos = __popc(bal & ((1u << lane) - 1u));
            if (eq && (taken + pos) < need) outp[cgt + taken + pos] = lane + 32 * j;
            taken += __popc(bal);
        }
    }

    // ---- phase C: u/v projections for own 16 points (xrow still resident) ----
    constexpr int SH = (COUT == 128) ? 7 : 6;
    for (int i = t; i < 16 * COUT; i += 256) {
        int nl = i >> SH, o = i & (COUT - 1);
        const float* wr = W + (size_t)o * (2 * C);
        float u = 0.f, v = 0.f;
#pragma unroll
        for (int c = 0; c < C; c++) {
            float xv = xrow[nl * 64 + c];
            float w1 = wr[c];
            u = fmaf(w1, xv, u);
            v = fmaf(wr[C + c] - w1, xv, v);
        }
        size_t bn = (size_t)((b << 10) + n0 + nl);
        g_u[bn * COUT + o] = u;
        g_v[bn * COUT + o] = v;
    }
}

// =====================================================================================
// back_kernel: gather + stats + grid barrier + GN + leaky + write feat
// grid 256 blocks x 256 thr, 16 points/block.
// =====================================================================================
__global__ __launch_bounds__(256) void back_kernel(int Cout, int gsoff, unsigned int epoch,
                                                   const float* __restrict__ gnw,
                                                   const float* __restrict__ gnb,
                                                   float* __restrict__ feat, int choff) {
    __shared__ int sidx[16 * KNB];
    __shared__ double sacc[4];
    __shared__ double sg[4];
    int t = threadIdx.x, lane = t & 31;
    int TPP = Cout >> 2;              // 16 or 32 lanes per point
    int ppb = 256 / TPP;              // 16 or 8 points per pass
    int passes = 16 / ppb;            // 1 or 2
    int bn0 = blockIdx.x * 16;
    int b = bn0 >> 10;
    int o4 = t % TPP;
    int pl0 = t / TPP;

    if (t < 4) sacc[t] = 0.0;
    for (int i = t; i < 16 * KNB; i += 256) sidx[i] = g_idx[bn0 * KNB + i];
    __syncthreads();

    const float4* ub = (const float4*)g_u + (size_t)(b << 10) * TPP;
    int half = TPP >> 1;
    int g = o4 / half;
    float4 rymx[2], rymn[2];
    const float Kf = (float)KNB;

    for (int p = 0; p < passes; p++) {
        int pl = p * ppb + pl0;
        int bn = bn0 + pl;
        const int* myidx = sidx + pl * KNB;
        float4 mx = make_float4(-CUDART_INF_F, -CUDART_INF_F, -CUDART_INF_F, -CUDART_INF_F);
        float4 mn = make_float4(CUDART_INF_F, CUDART_INF_F, CUDART_INF_F, CUDART_INF_F);
        float4 s1 = make_float4(0, 0, 0, 0), s2 = make_float4(0, 0, 0, 0);
        for (int k = 0; k < KNB; k += 4) {
            float4 v0 = ub[(size_t)myidx[k] * TPP + o4];
            float4 v1 = ub[(size_t)myidx[k + 1] * TPP + o4];
            float4 v2 = ub[(size_t)myidx[k + 2] * TPP + o4];
            float4 v3 = ub[(size_t)myidx[k + 3] * TPP + o4];
#define ACC(vv) \
            mx.x = fmaxf(mx.x, vv.x); mn.x = fminf(mn.x, vv.x); s1.x += vv.x; s2.x = fmaf(vv.x, vv.x, s2.x); \
            mx.y = fmaxf(mx.y, vv.y); mn.y = fminf(mn.y, vv.y); s1.y += vv.y; s2.y = fmaf(vv.y, vv.y, s2.y); \
            mx.z = fmaxf(mx.z, vv.z); mn.z = fminf(mn.z, vv.z); s1.z += vv.z; s2.z = fmaf(vv.z, vv.z, s2.z); \
            mx.w = fmaxf(mx.w, vv.w); mn.w = fminf(mn.w, vv.w); s1.w += vv.w; s2.w = fmaf(vv.w, vv.w, s2.w);
            ACC(v0) ACC(v1) ACC(v2) ACC(v3)
#undef ACC
        }
        float4 v = ((const float4*)g_v)[(size_t)bn * TPP + o4];
        rymx[p] = make_float4(mx.x + v.x, mx.y + v.y, mx.z + v.z, mx.w + v.w);
        rymn[p] = make_float4(mn.x + v.x, mn.y + v.y, mn.z + v.z, mn.w + v.w);
        float S1 = (s1.x + Kf * v.x) + (s1.y + Kf * v.y) + (s1.z + Kf * v.z) + (s1.w + Kf * v.w);
        float S2 = (s2.x + 2.f * v.x * s1.x + Kf * v.x * v.x)
                 + (s2.y + 2.f * v.y * s1.y + Kf * v.y * v.y)
                 + (s2.z + 2.f * v.z * s1.z + Kf * v.z * v.z)
                 + (s2.w + 2.f * v.w * s1.w + Kf * v.w * v.w);
#pragma unroll
        for (int off = 8; off > 0; off >>= 1) {
            if (off < half) {
                S1 += __shfl_down_sync(0xffffffffu, S1, off, half);
                S2 += __shfl_down_sync(0xffffffffu, S2, off, half);
            }
        }
        if ((lane & (half - 1)) == 0) {
            int gg = (lane / half) & 1;
            atomicAdd(&sacc[gg * 2 + 0], (double)S1);
            atomicAdd(&sacc[gg * 2 + 1], (double)S2);
        }
    }
    __syncthreads();
    if (t < 4) atomicAdd(&g_gs[gsoff + (b * 2 + (t >> 1)) * 2 + (t & 1)], sacc[t]);

    grid_barrier(epoch, 256u);

    // one L2 read per value per block, broadcast via smem (NOT per-thread atomics)
    if (t < 4) sg[t] = __ldcg(&g_gs[gsoff + (b * 2 + (t >> 1)) * 2 + (t & 1)]);
    __syncthreads();

    double cntr = (double)(Cout >> 1) * (double)NPTS * (double)KNB;
    double S1g = sg[g * 2 + 0];
    double S2g = sg[g * 2 + 1];
    double mud = S1g / cntr;
    float var = (float)(S2g / cntr - mud * mud);
    float rsq = rsqrtf(var + 1e-5f);
    float mu = (float)mud;
    float A[4], Bb[4];
#pragma unroll
    for (int j = 0; j < 4; j++) {
        int o = 4 * o4 + j;
        A[j] = gnw[o] * rsq;
        Bb[j] = gnb[o] - mu * A[j];
    }
    for (int p = 0; p < passes; p++) {
        int pl = p * ppb + pl0;
        int n = (bn0 & 1023) + pl;
        float* fb = feat + (size_t)b * 262144 + (size_t)choff * NPTS + n;
        float mxv[4] = { rymx[p].x, rymx[p].y, rymx[p].z, rymx[p].w };
        float mnv[4] = { rymn[p].x, rymn[p].y, rymn[p].z, rymn[p].w };
#pragma unroll
        for (int j = 0; j < 4; j++) {
            float c1 = fmaf(A[j], mxv[j], Bb[j]);
            float c2 = fmaf(A[j], mnv[j], Bb[j]);
            c1 = c1 >= 0.f ? c1 : 0.2f * c1;
            c2 = c2 >= 0.f ? c2 : 0.2f * c2;
            fb[(size_t)(4 * o4 + j) * NPTS] = fmaxf(c1, c2);
        }
    }
}

// =====================================================================================
// tail_kernel: final matmul (128x128 tiles) + stats + grid barrier + GN/relu/max output
// =====================================================================================
__global__ __launch_bounds__(256, 2) void tail_kernel(const float* __restrict__ feat,
                                                      const float* __restrict__ W,
                                                      const float* __restrict__ bias,
                                                      const float* __restrict__ gnw,
                                                      const float* __restrict__ gnb,
                                                      float* __restrict__ out) {
    int b = blockIdx.z;
    int co0 = blockIdx.x * 128, n0 = blockIdx.y * 128;
    __shared__ float Ws[32][132];
    __shared__ float Xs[32][128];
    int t = threadIdx.x, tx = t & 15, ty = t >> 4;
    int lane = t & 31, w = t >> 5;
    float acc[8][8] = {};
    const float* fb = feat + (size_t)b * 262144;
    for (int cc = 0; cc < 256; cc += 32) {
        for (int i = t; i < 32 * 128; i += 256) {
            int row = i >> 5, c = i & 31;
            Ws[c][row] = W[(size_t)(co0 + row) * 256 + cc + c];
        }
        for (int i = t; i < 32 * 128; i += 256) {
            int nl = i & 127, c = i >> 7;
            Xs[c][nl] = fb[(size_t)(cc + c) * NPTS + n0 + nl];
        }
        __syncthreads();
#pragma unroll
        for (int c = 0; c < 32; c++) {
            float wv[8], xv[8];
            const float4* w4 = (const float4*)&Ws[c][ty * 8];
            const float4* x4 = (const float4*)&Xs[c][tx * 8];
            float4 p0 = w4[0], p1 = w4[1], q0 = x4[0], q1 = x4[1];
            wv[0]=p0.x;wv[1]=p0.y;wv[2]=p0.z;wv[3]=p0.w;wv[4]=p1.x;wv[5]=p1.y;wv[6]=p1.z;wv[7]=p1.w;
            xv[0]=q0.x;xv[1]=q0.y;xv[2]=q0.z;xv[3]=q0.w;xv[4]=q1.x;xv[5]=q1.y;xv[6]=q1.z;xv[7]=q1.w;
#pragma unroll
            for (int i = 0; i < 8; i++)
#pragma unroll
                for (int j = 0; j < 8; j++) acc[i][j] = fmaf(wv[i], xv[j], acc[i][j]);
        }
        __syncthreads();
    }
    float s1t = 0.f, s2t = 0.f;
#pragma unroll
    for (int i = 0; i < 8; i++) {
        int co = co0 + ty * 8 + i;
        float bv = bias[co];
        float mx = -CUDART_INF_F, mn = CUDART_INF_F;
#pragma unroll
        for (int j = 0; j < 8; j++) {
            float y = acc[i][j] + bv;
            mx = fmaxf(mx, y); mn = fminf(mn, y);
            s1t += y; s2t = fmaf(y, y, s2t);
        }
#pragma unroll
        for (int off = 8; off > 0; off >>= 1) {
            mx = fmaxf(mx, __shfl_down_sync(0xffffffffu, mx, off, 16));
            mn = fminf(mn, __shfl_down_sync(0xffffffffu, mn, off, 16));
        }
        if (tx == 0) {
            atomicMax(&g_ymax[b * 1024 + co], fenc(mx));
            atomicMin(&g_ymin[b * 1024 + co], fenc(mn));
        }
    }
#pragma unroll
    for (int off = 16; off > 0; off >>= 1) {
        s1t += __shfl_down_sync(0xffffffffu, s1t, off);
        s2t += __shfl_down_sync(0xffffffffu, s2t, off);
    }
    __shared__ double sred[8][2];
    if (lane == 0) { sred[w][0] = (double)s1t; sred[w][1] = (double)s2t; }
    __syncthreads();
    if (t == 0) {
        double a = 0.0, c = 0.0;
        for (int i = 0; i < 8; i++) { a += sred[i][0]; c += sred[i][1]; }
        atomicAdd(&g_gs5[(b * 8 + blockIdx.x) * 2 + 0], a);
        atomicAdd(&g_gs5[(b * 8 + blockIdx.x) * 2 + 1], c);
    }

    grid_barrier(4u, 256u);

    if (t < 16) {
        int bid = blockIdx.x + (blockIdx.y << 3) + ((int)blockIdx.z << 6);
        int i = bid * 16 + t;
        int ob = i >> 10, c = i & 1023;
        int g = c >> 7;
        double cntr = 128.0 * 1024.0;
        double S1 = __ldcg(&g_gs5[(ob * 8 + g) * 2 + 0]);
        double S2 = __ldcg(&g_gs5[(ob * 8 + g) * 2 + 1]);
        double mud = S1 / cntr;
        float var = (float)(S2 / cntr - mud * mud);
        float rsq = rsqrtf(var + 1e-5f);
        float a = gnw[c] * rsq;
        float bb = gnb[c] - (float)mud * a;
        float ymx = fdec(__ldcg(&g_ymax[i]));
        float ymn = fdec(__ldcg(&g_ymin[i]));
        float c1 = fmaxf(fmaf(a, ymx, bb), 0.f);
        float c2 = fmaxf(fmaf(a, ymn, bb), 0.f);
        out[i] = fmaxf(c1, c2);
    }
}

// ---------------- launch ----------------
extern "C" void kernel_launch(void* const* d_in, const int* in_sizes, int n_in,
                              void* d_out, int out_size) {
    const float* x    = (const float*)d_in[0];
    const float* c1w  = (const float*)d_in[1];
    const float* g1w  = (const float*)d_in[2];
    const float* g1b  = (const float*)d_in[3];
    const float* c2w  = (const float*)d_in[4];
    const float* g2w  = (const float*)d_in[5];
    const float* g2b  = (const float*)d_in[6];
    const float* c3w  = (const float*)d_in[7];
    const float* g3w  = (const float*)d_in[8];
    const float* g3b  = (const float*)d_in[9];
    const float* mlpw = (const float*)d_in[10];
    const float* mlpb = (const float*)d_in[11];
    const float* g5w  = (const float*)d_in[12];
    const float* g5b  = (const float*)d_in[13];

    float* out  = (float*)d_out;
    float* feat = out + B * 1024;  // x_features region (B,256,N)

    cudaFuncSetAttribute(front_kernel<3, 64>,  cudaFuncAttributeMaxDynamicSharedMemorySize, FRONT_SMEM);
    cudaFuncSetAttribute(front_kernel<64, 64>, cudaFuncAttributeMaxDynamicSharedMemorySize, FRONT_SMEM);
    cudaFuncSetAttribute(front_kernel<64, 128>, cudaFuncAttributeMaxDynamicSharedMemorySize, FRONT_SMEM);

    zero_all_kernel<<<16, 256>>>();

    // layer 1
    front_kernel<3, 64><<<dim3(64, B), 256, FRONT_SMEM>>>(x, 3 * NPTS, c1w);
    back_kernel<<<256, 256>>>(64, 0, 1u, g1w, g1b, feat, 0);
    // layer 2
    front_kernel<64, 64><<<dim3(64, B), 256, FRONT_SMEM>>>(feat, 256 * NPTS, c2w);
    back_kernel<<<256, 256>>>(64, 16, 2u, g2w, g2b, feat, 64);
    // layer 3
    front_kernel<64, 128><<<dim3(64, B), 256, FRONT_SMEM>>>(feat + 64 * NPTS, 256 * NPTS, c3w);
    back_kernel<<<256, 256>>>(128, 32, 3u, g3w, g3b, feat, 128);

    tail_kernel<<<dim3(8, 8, B), 256>>>(feat, mlpw, mlpb, g5w, g5b, out);
}

// round 10
// speedup vs baseline: 1.4649x; 1.0526x over previous
#include <cuda_runtime.h>
#include <cuda_bf16.h>
#include <math_constants.h>

#define B 4
#define NPTS 1024
#define KNB 80

// ---------------- scratch (device globals) ----------------
__device__ float g_G[(size_t)B * NPTS * NPTS];   // neg_dist matrices
__device__ int   g_idx[B * NPTS * KNB];
__device__ float g_u[(size_t)B * NPTS * 128];
__device__ float g_v[(size_t)B * NPTS * 128];
__device__ double g_gs[48];
__device__ unsigned int g_ymax[B * 1024];
__device__ unsigned int g_ymin[B * 1024];
__device__ double g_gs5[64];
__device__ unsigned int g_cnt;
__device__ unsigned int g_flag;

__device__ __forceinline__ unsigned int fenc(float f) {
    unsigned int b = __float_as_uint(f);
    return (b & 0x80000000u) ? ~b : (b | 0x80000000u);
}
__device__ __forceinline__ float fdec(unsigned int u) {
    unsigned int b = (u & 0x80000000u) ? (u & 0x7FFFFFFFu) : ~u;
    return __uint_as_float(b);
}

// software grid barrier (co-resident grids only; epoch monotone per replay)
__device__ __forceinline__ void grid_barrier(unsigned int epoch, unsigned int nb) {
    __threadfence();
    __syncthreads();
    if (threadIdx.x == 0) {
        unsigned int a = atomicAdd(&g_cnt, 1u);
        if (a == nb - 1u) { g_cnt = 0u; __threadfence(); atomicExch(&g_flag, epoch); }
        while (atomicAdd(&g_flag, 0u) < epoch) __nanosleep(64);
    }
    __syncthreads();
}

// ---------------- zero/re-arm kernel (runs first every replay) ----------------
__global__ void zero_all_kernel() {
    int i = blockIdx.x * 256 + threadIdx.x;
    if (i < B * 1024) { g_ymax[i] = 0u; g_ymin[i] = 0xFFFFFFFFu; }
    if (i < 48) g_gs[i] = 0.0;
    if (i < 64) g_gs5[i] = 0.0;
    if (i == 0) { g_cnt = 0u; g_flag = 0u; }
}

// ---------------- gram + fused xx: writes neg_dist = 2*x^T x - xx_n - xx_m ----------------
// 128x128 tile, 256 threads, 8x8 per thread  (r3-proven)
__global__ __launch_bounds__(256) void gram_kernel(const float* __restrict__ x, int bstride, int C) {
    int b = blockIdx.z;
    int n0 = blockIdx.y * 128, m0 = blockIdx.x * 128;
    __shared__ float As[32][132];
    __shared__ float Bs[32][132];
    int t = threadIdx.x;
    int tx = t & 15, ty = t >> 4;
    float acc[8][8] = {};
    float sa[8] = {}, sb[8] = {};
    const float* xb = x + (size_t)b * bstride;
    for (int cc = 0; cc < C; cc += 32) {
        int CH = min(32, C - cc);
        for (int i = t; i < 32 * 128; i += 256) {
            int c = i >> 7, l = i & 127;
            float av = 0.f, bv = 0.f;
            if (c < CH) {
                av = xb[(size_t)(cc + c) * NPTS + n0 + l];
                bv = xb[(size_t)(cc + c) * NPTS + m0 + l];
            }
            As[c][l] = av; Bs[c][l] = bv;
        }
        __syncthreads();
        for (int c = 0; c < CH; c++) {
            float a[8], bb[8];
            const float4* a4 = (const float4*)&As[c][ty * 8];
            const float4* b4 = (const float4*)&Bs[c][tx * 8];
            float4 av0 = a4[0], av1 = a4[1];
            float4 bv0 = b4[0], bv1 = b4[1];
            a[0]=av0.x;a[1]=av0.y;a[2]=av0.z;a[3]=av0.w;a[4]=av1.x;a[5]=av1.y;a[6]=av1.z;a[7]=av1.w;
            bb[0]=bv0.x;bb[1]=bv0.y;bb[2]=bv0.z;bb[3]=bv0.w;bb[4]=bv1.x;bb[5]=bv1.y;bb[6]=bv1.z;bb[7]=bv1.w;
#pragma unroll
            for (int i = 0; i < 8; i++) sa[i] = fmaf(a[i], a[i], sa[i]);
#pragma unroll
            for (int j = 0; j < 8; j++) sb[j] = fmaf(bb[j], bb[j], sb[j]);
#pragma unroll
            for (int i = 0; i < 8; i++)
#pragma unroll
                for (int j = 0; j < 8; j++) acc[i][j] = fmaf(a[i], bb[j], acc[i][j]);
        }
        __syncthreads();
    }
    float* Gb = g_G + ((size_t)b << 20);
#pragma unroll
    for (int i = 0; i < 8; i++) {
        float* row = Gb + (size_t)(n0 + ty * 8 + i) * NPTS + m0 + tx * 8;
#pragma unroll
        for (int j = 0; j < 8; j++)
            row[j] = 2.f * acc[i][j] - sa[i] - sb[j];
    }
}

// ---------------- knn: top-80 per row, 4-pass radix select, warp-aggregated (r3) ----------------
__global__ __launch_bounds__(256) void knn_kernel() {
    int bn = blockIdx.x;
    int b = bn >> 10;
    __shared__ unsigned int skeys[NPTS];
    __shared__ int hist[256];
    __shared__ int wtot[8];
    __shared__ int s_bsel, s_above, s_cnt, s_ecnt;
    __shared__ int s_eq[128];
    const float4* nd4 = (const float4*)(g_G + ((size_t)b << 20) + ((size_t)(bn & 1023) << 10));
    int t = threadIdx.x;
    int lane = t & 31, w = t >> 5;
    float4 d = nd4[t];
    unsigned int rkeys[4] = { fenc(d.x), fenc(d.y), fenc(d.z), fenc(d.w) };
    ((uint4*)skeys)[t] = make_uint4(rkeys[0], rkeys[1], rkeys[2], rkeys[3]);
    unsigned int prefix = 0, pmask = 0;
    int need = KNB;
    for (int shift = 24; shift >= 0; shift -= 8) {
        hist[t] = 0;
        __syncthreads();
#pragma unroll
        for (int j = 0; j < 4; j++) {
            unsigned int k = rkeys[j];
            bool act = ((k & pmask) == prefix);
            int bin = act ? (int)((k >> shift) & 255) : (300 + j);
            unsigned int m = __match_any_sync(0xffffffffu, bin);
            if (act && ((m & ((1u << lane) - 1u)) == 0u))
                atomicAdd(&hist[bin], __popc(m));
        }
        __syncthreads();
        int c = hist[t];
        int s = c;
#pragma unroll
        for (int off = 1; off < 32; off <<= 1) {
            int o = __shfl_down_sync(0xffffffffu, s, off);
            if (lane + off < 32) s += o;
        }
        if (lane == 0) wtot[w] = s;
        __syncthreads();
        int offsum = 0;
        for (int w2 = w + 1; w2 < 8; w2++) offsum += wtot[w2];
        int sfx = s + offsum;
        int nxt = sfx - c;
        if (sfx >= need && nxt < need) { s_bsel = t; s_above = nxt; }
        __syncthreads();
        prefix |= ((unsigned int)s_bsel) << shift;
        pmask  |= 255u << shift;
        need   -= s_above;
        __syncthreads();
    }
    if (t == 0) { s_cnt = 0; s_ecnt = 0; }
    __syncthreads();
    int* out = g_idx + bn * KNB;
#pragma unroll
    for (int j = 0; j < 4; j++) {
        unsigned int k = rkeys[j];
        int idx = 4 * t + j;
        bool gt = (k > prefix);
        unsigned int bal = __ballot_sync(0xffffffffu, gt);
        if (bal) {
            int ldr = __ffs(bal) - 1;
            int base = 0;
            if (lane == ldr) base = atomicAdd(&s_cnt, __popc(bal));
            base = __shfl_sync(0xffffffffu, base, ldr);
            if (gt) out[base + __popc(bal & ((1u << lane) - 1u))] = idx;
        }
        bool eq = (k == prefix);
        unsigned int be = __ballot_sync(0xffffffffu, eq);
        if (be) {
            int ldr = __ffs(be) - 1;
            int base = 0;
            if (lane == ldr) base = atomicAdd(&s_ecnt, __popc(be));
            base = __shfl_sync(0xffffffffu, base, ldr);
            if (eq) {
                int p = base + __popc(be & ((1u << lane) - 1u));
                if (p < 128) s_eq[p] = idx;
            }
        }
    }
    __syncthreads();
    if (t == 0) {
        int p = s_cnt;           // == KNB - need
        int L = s_ecnt;
        if (L == need && L <= 128) {
            for (int i = 0; i < L; i++) out[p++] = s_eq[i];
        } else if (L <= 128) {
            for (int r = 0; r < need; r++) {
                int bi = -1, bv = 0x7FFFFFFF;
                for (int i = 0; i < L; i++) {
                    int v = s_eq[i];
                    if (v >= 0 && v < bv) { bv = v; bi = i; }
                }
                out[p++] = bv;
                s_eq[bi] = -1;
            }
        } else {
            for (int i = 0; i < NPTS && p < KNB; i++)
                if (skeys[i] == prefix) out[p++] = i;
        }
    }
}

// ---------------- u/v projections (r3-proven, 5.4us) ----------------
__global__ void uv_kernel(const float* __restrict__ x, int bstride,
                          const float* __restrict__ W, int Cin, int Cout) {
    int tid = blockIdx.x * blockDim.x + threadIdx.x;
    int total = B * NPTS * Cout;
    if (tid >= total) return;
    int o = tid % Cout;
    int n = (tid / Cout) & 1023;
    int b = tid / (Cout * NPTS);
    const float* xb = x + (size_t)b * bstride + n;
    const float* w = W + (size_t)o * 2 * Cin;
    float u = 0.f, v = 0.f;
    for (int c = 0; c < Cin; c++) {
        float xv = xb[(size_t)c * NPTS];
        float w1 = w[c], w2 = w[Cin + c];
        u = fmaf(w1, xv, u);
        v = fmaf(w2 - w1, xv, v);
    }
    g_u[tid] = u;
    g_v[tid] = v;
}

// =====================================================================================
// back_kernel (r9-proven fast): gather + stats + grid barrier + GN + leaky + write feat
// grid 256 blocks x 256 thr, 16 points/block.
// =====================================================================================
__global__ __launch_bounds__(256) void back_kernel(int Cout, int gsoff, unsigned int epoch,
                                                   const float* __restrict__ gnw,
                                                   const float* __restrict__ gnb,
                                                   float* __restrict__ feat, int choff) {
    __shared__ int sidx[16 * KNB];
    __shared__ double sacc[4];
    __shared__ double sg[4];
    int t = threadIdx.x, lane = t & 31;
    int TPP = Cout >> 2;              // 16 or 32 lanes per point
    int ppb = 256 / TPP;              // 16 or 8 points per pass
    int passes = 16 / ppb;            // 1 or 2
    int bn0 = blockIdx.x * 16;
    int b = bn0 >> 10;
    int o4 = t % TPP;
    int pl0 = t / TPP;

    if (t < 4) sacc[t] = 0.0;
    for (int i = t; i < 16 * KNB; i += 256) sidx[i] = g_idx[bn0 * KNB + i];
    __syncthreads();

    const float4* ub = (const float4*)g_u + (size_t)(b << 10) * TPP;
    int half = TPP >> 1;
    int g = o4 / half;
    float4 rymx[2], rymn[2];
    const float Kf = (float)KNB;

    for (int p = 0; p < passes; p++) {
        int pl = p * ppb + pl0;
        int bn = bn0 + pl;
        const int* myidx = sidx + pl * KNB;
        float4 mx = make_float4(-CUDART_INF_F, -CUDART_INF_F, -CUDART_INF_F, -CUDART_INF_F);
        float4 mn = make_float4(CUDART_INF_F, CUDART_INF_F, CUDART_INF_F, CUDART_INF_F);
        float4 s1 = make_float4(0, 0, 0, 0), s2 = make_float4(0, 0, 0, 0);
        for (int k = 0; k < KNB; k += 4) {
            float4 v0 = ub[(size_t)myidx[k] * TPP + o4];
            float4 v1 = ub[(size_t)myidx[k + 1] * TPP + o4];
            float4 v2 = ub[(size_t)myidx[k + 2] * TPP + o4];
            float4 v3 = ub[(size_t)myidx[k + 3] * TPP + o4];
#define ACC(vv) \
            mx.x = fmaxf(mx.x, vv.x); mn.x = fminf(mn.x, vv.x); s1.x += vv.x; s2.x = fmaf(vv.x, vv.x, s2.x); \
            mx.y = fmaxf(mx.y, vv.y); mn.y = fminf(mn.y, vv.y); s1.y += vv.y; s2.y = fmaf(vv.y, vv.y, s2.y); \
            mx.z = fmaxf(mx.z, vv.z); mn.z = fminf(mn.z, vv.z); s1.z += vv.z; s2.z = fmaf(vv.z, vv.z, s2.z); \
            mx.w = fmaxf(mx.w, vv.w); mn.w = fminf(mn.w, vv.w); s1.w += vv.w; s2.w = fmaf(vv.w, vv.w, s2.w);
            ACC(v0) ACC(v1) ACC(v2) ACC(v3)
#undef ACC
        }
        float4 v = ((const float4*)g_v)[(size_t)bn * TPP + o4];
        rymx[p] = make_float4(mx.x + v.x, mx.y + v.y, mx.z + v.z, mx.w + v.w);
        rymn[p] = make_float4(mn.x + v.x, mn.y + v.y, mn.z + v.z, mn.w + v.w);
        float S1 = (s1.x + Kf * v.x) + (s1.y + Kf * v.y) + (s1.z + Kf * v.z) + (s1.w + Kf * v.w);
        float S2 = (s2.x + 2.f * v.x * s1.x + Kf * v.x * v.x)
                 + (s2.y + 2.f * v.y * s1.y + Kf * v.y * v.y)
                 + (s2.z + 2.f * v.z * s1.z + Kf * v.z * v.z)
                 + (s2.w + 2.f * v.w * s1.w + Kf * v.w * v.w);
#pragma unroll
        for (int off = 8; off > 0; off >>= 1) {
            if (off < half) {
                S1 += __shfl_down_sync(0xffffffffu, S1, off, half);
                S2 += __shfl_down_sync(0xffffffffu, S2, off, half);
            }
        }
        if ((lane & (half - 1)) == 0) {
            int gg = (lane / half) & 1;
            atomicAdd(&sacc[gg * 2 + 0], (double)S1);
            atomicAdd(&sacc[gg * 2 + 1], (double)S2);
        }
    }
    __syncthreads();
    if (t < 4) atomicAdd(&g_gs[gsoff + (b * 2 + (t >> 1)) * 2 + (t & 1)], sacc[t]);

    grid_barrier(epoch, 256u);

    // one L2 read per value per block, broadcast via smem
    if (t < 4) sg[t] = __ldcg(&g_gs[gsoff + (b * 2 + (t >> 1)) * 2 + (t & 1)]);
    __syncthreads();

    double cntr = (double)(Cout >> 1) * (double)NPTS * (double)KNB;
    double S1g = sg[g * 2 + 0];
    double S2g = sg[g * 2 + 1];
    double mud = S1g / cntr;
    float var = (float)(S2g / cntr - mud * mud);
    float rsq = rsqrtf(var + 1e-5f);
    float mu = (float)mud;
    float A[4], Bb[4];
#pragma unroll
    for (int j = 0; j < 4; j++) {
        int o = 4 * o4 + j;
        A[j] = gnw[o] * rsq;
        Bb[j] = gnb[o] - mu * A[j];
    }
    for (int p = 0; p < passes; p++) {
        int pl = p * ppb + pl0;
        int n = (bn0 & 1023) + pl;
        float* fb = feat + (size_t)b * 262144 + (size_t)choff * NPTS + n;
        float mxv[4] = { rymx[p].x, rymx[p].y, rymx[p].z, rymx[p].w };
        float mnv[4] = { rymn[p].x, rymn[p].y, rymn[p].z, rymn[p].w };
#pragma unroll
        for (int j = 0; j < 4; j++) {
            float c1 = fmaf(A[j], mxv[j], Bb[j]);
            float c2 = fmaf(A[j], mnv[j], Bb[j]);
            c1 = c1 >= 0.f ? c1 : 0.2f * c1;
            c2 = c2 >= 0.f ? c2 : 0.2f * c2;
            fb[(size_t)(4 * o4 + j) * NPTS] = fmaxf(c1, c2);
        }
    }
}

// =====================================================================================
// tail_kernel (r9-proven): final matmul + stats + grid barrier + GN/relu/max output
// =====================================================================================
__global__ __launch_bounds__(256, 2) void tail_kernel(const float* __restrict__ feat,
                                                      const float* __restrict__ W,
                                                      const float* __restrict__ bias,
                                                      const float* __restrict__ gnw,
                                                      const float* __restrict__ gnb,
                                                      float* __restrict__ out) {
    int b = blockIdx.z;
    int co0 = blockIdx.x * 128, n0 = blockIdx.y * 128;
    __shared__ float Ws[32][132];
    __shared__ float Xs[32][128];
    int t = threadIdx.x, tx = t & 15, ty = t >> 4;
    int lane = t & 31, w = t >> 5;
    float acc[8][8] = {};
    const float* fb = feat + (size_t)b * 262144;
    for (int cc = 0; cc < 256; cc += 32) {
        for (int i = t; i < 32 * 128; i += 256) {
            int row = i >> 5, c = i & 31;
            Ws[c][row] = W[(size_t)(co0 + row) * 256 + cc + c];
        }
        for (int i = t; i < 32 * 128; i += 256) {
            int nl = i & 127, c = i >> 7;
            Xs[c][nl] = fb[(size_t)(cc + c) * NPTS + n0 + nl];
        }
        __syncthreads();
#pragma unroll
        for (int c = 0; c < 32; c++) {
            float wv[8], xv[8];
            const float4* w4 = (const float4*)&Ws[c][ty * 8];
            const float4* x4 = (const float4*)&Xs[c][tx * 8];
            float4 p0 = w4[0], p1 = w4[1], q0 = x4[0], q1 = x4[1];
            wv[0]=p0.x;wv[1]=p0.y;wv[2]=p0.z;wv[3]=p0.w;wv[4]=p1.x;wv[5]=p1.y;wv[6]=p1.z;wv[7]=p1.w;
            xv[0]=q0.x;xv[1]=q0.y;xv[2]=q0.z;xv[3]=q0.w;xv[4]=q1.x;xv[5]=q1.y;xv[6]=q1.z;xv[7]=q1.w;
#pragma unroll
            for (int i = 0; i < 8; i++)
#pragma unroll
                for (int j = 0; j < 8; j++) acc[i][j] = fmaf(wv[i], xv[j], acc[i][j]);
        }
        __syncthreads();
    }
    float s1t = 0.f, s2t = 0.f;
#pragma unroll
    for (int i = 0; i < 8; i++) {
        int co = co0 + ty * 8 + i;
        float bv = bias[co];
        float mx = -CUDART_INF_F, mn = CUDART_INF_F;
#pragma unroll
        for (int j = 0; j < 8; j++) {
            float y = acc[i][j] + bv;
            mx = fmaxf(mx, y); mn = fminf(mn, y);
            s1t += y; s2t = fmaf(y, y, s2t);
        }
#pragma unroll
        for (int off = 8; off > 0; off >>= 1) {
            mx = fmaxf(mx, __shfl_down_sync(0xffffffffu, mx, off, 16));
            mn = fminf(mn, __shfl_down_sync(0xffffffffu, mn, off, 16));
        }
        if (tx == 0) {
            atomicMax(&g_ymax[b * 1024 + co], fenc(mx));
            atomicMin(&g_ymin[b * 1024 + co], fenc(mn));
        }
    }
#pragma unroll
    for (int off = 16; off > 0; off >>= 1) {
        s1t += __shfl_down_sync(0xffffffffu, s1t, off);
        s2t += __shfl_down_sync(0xffffffffu, s2t, off);
    }
    __shared__ double sred[8][2];
    if (lane == 0) { sred[w][0] = (double)s1t; sred[w][1] = (double)s2t; }
    __syncthreads();
    if (t == 0) {
        double a = 0.0, c = 0.0;
        for (int i = 0; i < 8; i++) { a += sred[i][0]; c += sred[i][1]; }
        atomicAdd(&g_gs5[(b * 8 + blockIdx.x) * 2 + 0], a);
        atomicAdd(&g_gs5[(b * 8 + blockIdx.x) * 2 + 1], c);
    }

    grid_barrier(4u, 256u);

    if (t < 16) {
        int bid = blockIdx.x + (blockIdx.y << 3) + ((int)blockIdx.z << 6);
        int i = bid * 16 + t;
        int ob = i >> 10, c = i & 1023;
        int g = c >> 7;
        double cntr = 128.0 * 1024.0;
        double S1 = __ldcg(&g_gs5[(ob * 8 + g) * 2 + 0]);
        double S2 = __ldcg(&g_gs5[(ob * 8 + g) * 2 + 1]);
        double mud = S1 / cntr;
        float var = (float)(S2 / cntr - mud * mud);
        float rsq = rsqrtf(var + 1e-5f);
        float a = gnw[c] * rsq;
        float bb = gnb[c] - (float)mud * a;
        float ymx = fdec(__ldcg(&g_ymax[i]));
        float ymn = fdec(__ldcg(&g_ymin[i]));
        float c1 = fmaxf(fmaf(a, ymx, bb), 0.f);
        float c2 = fmaxf(fmaf(a, ymn, bb), 0.f);
        out[i] = fmaxf(c1, c2);
    }
}

// ---------------- launch ----------------
extern "C" void kernel_launch(void* const* d_in, const int* in_sizes, int n_in,
                              void* d_out, int out_size) {
    const float* x    = (const float*)d_in[0];
    const float* c1w  = (const float*)d_in[1];
    const float* g1w  = (const float*)d_in[2];
    const float* g1b  = (const float*)d_in[3];
    const float* c2w  = (const float*)d_in[4];
    const float* g2w  = (const float*)d_in[5];
    const float* g2b  = (const float*)d_in[6];
    const float* c3w  = (const float*)d_in[7];
    const float* g3w  = (const float*)d_in[8];
    const float* g3b  = (const float*)d_in[9];
    const float* mlpw = (const float*)d_in[10];
    const float* mlpb = (const float*)d_in[11];
    const float* g5w  = (const float*)d_in[12];
    const float* g5b  = (const float*)d_in[13];

    float* out  = (float*)d_out;
    float* feat = out + B * 1024;  // x_features region (B,256,N)

    struct L { const float* xin; int bstride, Cin, Cout, choff, gsoff;
               const float* W; const float* gw; const float* gb; };
    L layers[3] = {
        { x,                3 * NPTS,   3,  64,  0,   0,  c1w, g1w, g1b },
        { feat,             256 * NPTS, 64, 64,  64,  16, c2w, g2w, g2b },
        { feat + 64 * NPTS, 256 * NPTS, 64, 128, 128, 32, c3w, g3w, g3b },
    };

    zero_all_kernel<<<16, 256>>>();

    for (int li = 0; li < 3; li++) {
        L& l = layers[li];
        gram_kernel<<<dim3(8, 8, B), 256>>>(l.xin, l.bstride, l.Cin);
        knn_kernel<<<B * NPTS, 256>>>();
        int tot = B * NPTS * l.Cout;
        uv_kernel<<<tot / 256, 256>>>(l.xin, l.bstride, l.W, l.Cin, l.Cout);
        back_kernel<<<256, 256>>>(l.Cout, l.gsoff, (unsigned int)(li + 1), l.gw, l.gb, feat, l.choff);
    }

    tail_kernel<<<dim3(8, 8, B), 256>>>(feat, mlpw, mlpb, g5w, g5b, out);
}